// round 6
// baseline (speedup 1.0000x reference)
#include <cuda_runtime.h>
#include <math.h>

#define BB 8
#define LLEN 1024
#define DMODEL 1024
#define NH 16
#define DHEAD 64

// ---------------- static scratch (no allocations allowed) ----------------
static __device__ float g_Q[(size_t)BB * NH * LLEN * DHEAD];     // 32 MB
static __device__ float g_K[(size_t)BB * NH * LLEN * DHEAD];     // 32 MB
static __device__ float g_V[(size_t)BB * NH * LLEN * DHEAD];     // 32 MB
static __device__ float g_ctx[(size_t)BB * LLEN * DMODEL];       // 32 MB
static __device__ float g_proj[(size_t)BB * LLEN * DMODEL];      // 32 MB
static __device__ float g_attn[(size_t)BB * NH * LLEN * LLEN];   // 512 MB fallback

// ---------------- tf32 warp-MMA helpers ----------------
__device__ __forceinline__ unsigned f2tf32(float x) {
    unsigned r;
    asm("cvt.rna.tf32.f32 %0, %1;" : "=r"(r) : "f"(x));
    return r;
}

__device__ __forceinline__ void mma_tf32(float* d, const unsigned* a, const unsigned* b) {
    asm volatile(
        "mma.sync.aligned.m16n8k8.row.col.f32.tf32.tf32.f32 "
        "{%0,%1,%2,%3}, {%4,%5,%6,%7}, {%8,%9}, {%0,%1,%2,%3};\n"
        : "+f"(d[0]), "+f"(d[1]), "+f"(d[2]), "+f"(d[3])
        : "r"(a[0]), "r"(a[1]), "r"(a[2]), "r"(a[3]), "r"(b[0]), "r"(b[1]));
}

__device__ __forceinline__ void cp16(void* smem_dst, const void* gsrc) {
    unsigned s = (unsigned)__cvta_generic_to_shared(smem_dst);
    asm volatile("cp.async.ca.shared.global [%0], [%1], 16;\n" :: "r"(s), "l"(gsrc));
}
__device__ __forceinline__ void cp_commit() {
    asm volatile("cp.async.commit_group;\n");
}
template <int N>
__device__ __forceinline__ void cp_wait() {
    asm volatile("cp.async.wait_group %0;\n" :: "n"(N));
}

// =========================================================================
// Kernel 1: fused QKV projection, cp.async 2-stage pipeline. (R5, unchanged)
// =========================================================================
__global__ __launch_bounds__(256) void qkv_mma_kernel(
    const float* __restrict__ X,
    const float* __restrict__ Wq,
    const float* __restrict__ Wk,
    const float* __restrict__ Wv)
{
    __shared__ float As[2][128][20];
    __shared__ float Bs[2][16][136];

    const int tid  = threadIdx.x;
    const int warp = tid >> 5, lane = tid & 31;
    const int wm = warp >> 1, wn = warp & 1;
    const int g = lane >> 2, t = lane & 3;

    const int m0 = blockIdx.y * 128;
    const int ng = blockIdx.x * 128;
    const int wsel = ng >> 10;
    const int nl = ng & 1023;
    const float* __restrict__ W = (wsel == 0) ? Wq : (wsel == 1 ? Wk : Wv);

    const int am0 = (tid * 2) >> 2,      ach0 = ((tid * 2) & 3) * 4;
    const int am1 = (tid * 2 + 1) >> 2,  ach1 = ((tid * 2 + 1) & 3) * 4;
    const int bk0 = (tid * 2) >> 5,      bch0 = ((tid * 2) & 31) * 4;
    const int bk1 = (tid * 2 + 1) >> 5,  bch1 = ((tid * 2 + 1) & 31) * 4;

    float acc[2][8][4];
#pragma unroll
    for (int i = 0; i < 2; i++)
#pragma unroll
        for (int j = 0; j < 8; j++)
#pragma unroll
            for (int c = 0; c < 4; c++) acc[i][j][c] = 0.f;

    cp16(&As[0][am0][ach0], &X[(size_t)(m0 + am0) * DMODEL + ach0]);
    cp16(&As[0][am1][ach1], &X[(size_t)(m0 + am1) * DMODEL + ach1]);
    cp16(&Bs[0][bk0][bch0], &W[(size_t)bk0 * DMODEL + nl + bch0]);
    cp16(&Bs[0][bk1][bch1], &W[(size_t)bk1 * DMODEL + nl + bch1]);
    cp_commit();

    const int NIT = DMODEL / 16;
    for (int it = 0; it < NIT; it++) {
        const int buf = it & 1;
        if (it + 1 < NIT) {
            const int k0 = (it + 1) * 16;
            cp16(&As[buf ^ 1][am0][ach0], &X[(size_t)(m0 + am0) * DMODEL + k0 + ach0]);
            cp16(&As[buf ^ 1][am1][ach1], &X[(size_t)(m0 + am1) * DMODEL + k0 + ach1]);
            cp16(&Bs[buf ^ 1][bk0][bch0], &W[(size_t)(k0 + bk0) * DMODEL + nl + bch0]);
            cp16(&Bs[buf ^ 1][bk1][bch1], &W[(size_t)(k0 + bk1) * DMODEL + nl + bch1]);
            cp_commit();
            cp_wait<1>();
        } else {
            cp_wait<0>();
        }
        __syncthreads();

#pragma unroll
        for (int ks = 0; ks < 16; ks += 8) {
            unsigned af[2][4], bf[8][2];
#pragma unroll
            for (int i = 0; i < 2; i++) {
                int mr = wm * 32 + i * 16;
                af[i][0] = f2tf32(As[buf][mr + g][ks + t]);
                af[i][1] = f2tf32(As[buf][mr + g + 8][ks + t]);
                af[i][2] = f2tf32(As[buf][mr + g][ks + t + 4]);
                af[i][3] = f2tf32(As[buf][mr + g + 8][ks + t + 4]);
            }
#pragma unroll
            for (int j = 0; j < 8; j++) {
                int nr = wn * 64 + j * 8;
                bf[j][0] = f2tf32(Bs[buf][ks + t][nr + g]);
                bf[j][1] = f2tf32(Bs[buf][ks + t + 4][nr + g]);
            }
#pragma unroll
            for (int i = 0; i < 2; i++)
#pragma unroll
                for (int j = 0; j < 8; j++) mma_tf32(acc[i][j], af[i], bf[j]);
        }
        __syncthreads();
    }

    float* __restrict__ dst = (wsel == 0) ? g_Q : (wsel == 1 ? g_K : g_V);
#pragma unroll
    for (int i = 0; i < 2; i++) {
        int r0 = m0 + wm * 32 + i * 16 + g;
        int b = r0 >> 10, l = r0 & 1023;
#pragma unroll
        for (int j = 0; j < 8; j++) {
            int cl = nl + wn * 64 + j * 8 + 2 * t;
            int h = cl >> 6, d = cl & 63;
            size_t base = ((size_t)(b * NH + h) * LLEN);
            float2 v0 = make_float2(acc[i][j][0], acc[i][j][1]);
            float2 v1 = make_float2(acc[i][j][2], acc[i][j][3]);
            *(float2*)&dst[(base + l) * DHEAD + d] = v0;
            *(float2*)&dst[(base + l + 8) * DHEAD + d] = v1;
        }
    }
}

// =========================================================================
// Kernel 2: FUSED scores + mask + softmax.  NOW 32 Q-rows per CTA with 512
// threads (16 warps) — halves per-head K re-streaming vs the 16-row version.
// Warp w owns cols [w*8, w*8+8) of each 128-col block; two 16-row m-tiles.
// acc = 8 blocks x 2 mtiles x 4 = 64 floats/thread (same as before).
// =========================================================================
__global__ __launch_bounds__(512) void fused_attn_kernel(
    const int* __restrict__ mask,
    float* __restrict__ attn_ext)
{
    __shared__ unsigned Qs[32][68];     //  8704 B
    __shared__ unsigned Ks[128][68];    // 34816 B
    __shared__ float    red[32][16];    //  2048 B

    const int tid  = threadIdx.x;
    const int warp = tid >> 5, lane = tid & 31;
    const int g = lane >> 2, t = lane & 3;

    const int bh = blockIdx.y;
    const int b  = bh / NH;
    const int m0 = blockIdx.x * 32;
    const float* __restrict__ Q = g_Q + (size_t)bh * LLEN * DHEAD;
    const float* __restrict__ K = g_K + (size_t)bh * LLEN * DHEAD;

    // load Q strip 32x64 (one float4 per thread)
    {
        int m = tid >> 4, kq = (tid & 15) * 4;
        const float4 v = *(const float4*)&Q[(size_t)(m0 + m) * DHEAD + kq];
        Qs[m][kq + 0] = f2tf32(v.x);
        Qs[m][kq + 1] = f2tf32(v.y);
        Qs[m][kq + 2] = f2tf32(v.z);
        Qs[m][kq + 3] = f2tf32(v.w);
    }

    float acc[8][2][4];
#pragma unroll
    for (int s = 0; s < 8; s++)
#pragma unroll
        for (int i = 0; i < 2; i++)
#pragma unroll
            for (int c = 0; c < 4; c++) acc[s][i][c] = 0.f;

    // ---------------- Phase A: S = Q K^T over 8 K-blocks ----------------
#pragma unroll
    for (int s = 0; s < 8; s++) {
        const int n0 = s * 128;
        __syncthreads();
#pragma unroll
        for (int r = 0; r < 4; r++) {
            int idx = tid + r * 512;
            int n = idx >> 4, kq = (idx & 15) * 4;
            const float4 v = *(const float4*)&K[(size_t)(n0 + n) * DHEAD + kq];
            Ks[n][kq + 0] = f2tf32(v.x);
            Ks[n][kq + 1] = f2tf32(v.y);
            Ks[n][kq + 2] = f2tf32(v.z);
            Ks[n][kq + 3] = f2tf32(v.w);
        }
        __syncthreads();

        const int nr = warp * 8;
#pragma unroll
        for (int ks = 0; ks < 64; ks += 8) {
            unsigned af[2][4], bf[2];
#pragma unroll
            for (int i = 0; i < 2; i++) {
                int mr = i * 16;
                af[i][0] = Qs[mr + g][ks + t];
                af[i][1] = Qs[mr + g + 8][ks + t];
                af[i][2] = Qs[mr + g][ks + t + 4];
                af[i][3] = Qs[mr + g + 8][ks + t + 4];
            }
            bf[0] = Ks[nr + g][ks + t];
            bf[1] = Ks[nr + g][ks + t + 4];
#pragma unroll
            for (int i = 0; i < 2; i++) mma_tf32(acc[s][i], af[i], bf);
        }
    }

    // ---------------- scale + mask + row max ----------------
    // acc[s][i][0..1] -> row m0+i*16+g,   cols col, col+1
    // acc[s][i][2..3] -> row m0+i*16+g+8, cols col, col+1
    const float scale = 0.125f;
    const int* __restrict__ mr0 = mask + ((size_t)b * LLEN + m0 + g) * LLEN;
    const int* __restrict__ mr1 = mask + ((size_t)b * LLEN + m0 + g + 8) * LLEN;
    const int* __restrict__ mr2 = mask + ((size_t)b * LLEN + m0 + 16 + g) * LLEN;
    const int* __restrict__ mr3 = mask + ((size_t)b * LLEN + m0 + 24 + g) * LLEN;

    float mx[4] = {-3e38f, -3e38f, -3e38f, -3e38f};
#pragma unroll
    for (int s = 0; s < 8; s++) {
        const int col = s * 128 + warp * 8 + 2 * t;
        {
            float* a = acc[s][0];
            const int2 ma = *(const int2*)&mr0[col];
            const int2 mb = *(const int2*)&mr1[col];
            a[0] = ma.x ? -1e9f : a[0] * scale;
            a[1] = ma.y ? -1e9f : a[1] * scale;
            a[2] = mb.x ? -1e9f : a[2] * scale;
            a[3] = mb.y ? -1e9f : a[3] * scale;
            mx[0] = fmaxf(mx[0], fmaxf(a[0], a[1]));
            mx[1] = fmaxf(mx[1], fmaxf(a[2], a[3]));
        }
        {
            float* a = acc[s][1];
            const int2 ma = *(const int2*)&mr2[col];
            const int2 mb = *(const int2*)&mr3[col];
            a[0] = ma.x ? -1e9f : a[0] * scale;
            a[1] = ma.y ? -1e9f : a[1] * scale;
            a[2] = mb.x ? -1e9f : a[2] * scale;
            a[3] = mb.y ? -1e9f : a[3] * scale;
            mx[2] = fmaxf(mx[2], fmaxf(a[0], a[1]));
            mx[3] = fmaxf(mx[3], fmaxf(a[2], a[3]));
        }
    }
#pragma unroll
    for (int r = 0; r < 4; r++) {
        mx[r] = fmaxf(mx[r], __shfl_xor_sync(0xffffffffu, mx[r], 1));
        mx[r] = fmaxf(mx[r], __shfl_xor_sync(0xffffffffu, mx[r], 2));
    }
    __syncthreads();
    if (t == 0) {
        red[g][warp]      = mx[0];
        red[g + 8][warp]  = mx[1];
        red[g + 16][warp] = mx[2];
        red[g + 24][warp] = mx[3];
    }
    __syncthreads();
    float M[4];
#pragma unroll
    for (int r = 0; r < 4; r++) {
        const int row = r * 8 + g;     // rows g, g+8, g+16, g+24
        float m = red[row][0];
#pragma unroll
        for (int w = 1; w < 16; w++) m = fmaxf(m, red[row][w]);
        M[r] = m;
    }
    __syncthreads();

    // ---------------- exp + row sum ----------------
    float sm[4] = {0.f, 0.f, 0.f, 0.f};
#pragma unroll
    for (int s = 0; s < 8; s++) {
        {
            float* a = acc[s][0];
            a[0] = __expf(a[0] - M[0]);
            a[1] = __expf(a[1] - M[0]);
            a[2] = __expf(a[2] - M[1]);
            a[3] = __expf(a[3] - M[1]);
            sm[0] += a[0] + a[1];
            sm[1] += a[2] + a[3];
        }
        {
            float* a = acc[s][1];
            a[0] = __expf(a[0] - M[2]);
            a[1] = __expf(a[1] - M[2]);
            a[2] = __expf(a[2] - M[3]);
            a[3] = __expf(a[3] - M[3]);
            sm[2] += a[0] + a[1];
            sm[3] += a[2] + a[3];
        }
    }
#pragma unroll
    for (int r = 0; r < 4; r++) {
        sm[r] += __shfl_xor_sync(0xffffffffu, sm[r], 1);
        sm[r] += __shfl_xor_sync(0xffffffffu, sm[r], 2);
    }
    if (t == 0) {
        red[g][warp]      = sm[0];
        red[g + 8][warp]  = sm[1];
        red[g + 16][warp] = sm[2];
        red[g + 24][warp] = sm[3];
    }
    __syncthreads();
    float inv[4];
#pragma unroll
    for (int r = 0; r < 4; r++) {
        const int row = r * 8 + g;
        float s = 0.f;
#pragma unroll
        for (int w = 0; w < 16; w++) s += red[row][w];
        inv[r] = 1.0f / s;
    }

    // ---------------- normalized single-pass P write ----------------
    float* __restrict__ P = attn_ext ? attn_ext : g_attn;
    float* __restrict__ pr0 = P + ((size_t)bh * LLEN + m0 + g) * LLEN;
    float* __restrict__ pr1 = P + ((size_t)bh * LLEN + m0 + g + 8) * LLEN;
    float* __restrict__ pr2 = P + ((size_t)bh * LLEN + m0 + 16 + g) * LLEN;
    float* __restrict__ pr3 = P + ((size_t)bh * LLEN + m0 + 24 + g) * LLEN;
#pragma unroll
    for (int s = 0; s < 8; s++) {
        const int col = s * 128 + warp * 8 + 2 * t;
        const float* a0 = acc[s][0];
        const float* a1 = acc[s][1];
        *(float2*)&pr0[col] = make_float2(a0[0] * inv[0], a0[1] * inv[0]);
        *(float2*)&pr1[col] = make_float2(a0[2] * inv[1], a0[3] * inv[1]);
        *(float2*)&pr2[col] = make_float2(a1[0] * inv[2], a1[1] * inv[2]);
        *(float2*)&pr3[col] = make_float2(a1[2] * inv[3], a1[3] * inv[3]);
    }
}

// =========================================================================
// Kernel 3: context = P @ V (tf32 MMA, cp.async 2-stage).  (R5, unchanged)
// =========================================================================
__global__ __launch_bounds__(256) void pv_mma_kernel(const float* __restrict__ attn_ext)
{
    __shared__ float Ps[2][128][20];
    __shared__ float Vs[2][16][72];

    const int tid  = threadIdx.x;
    const int warp = tid >> 5, lane = tid & 31;
    const int wm = warp >> 1, wn = warp & 1;
    const int g = lane >> 2, t = lane & 3;

    const int bh = blockIdx.y;
    const int m0 = blockIdx.x * 128;
    const float* __restrict__ P =
        (attn_ext ? attn_ext : (const float*)g_attn) + (size_t)bh * LLEN * LLEN;
    const float* __restrict__ V = g_V + (size_t)bh * LLEN * DHEAD;

    const int prow = tid >> 2, pc4 = (tid & 3) * 4;
    const int vrow = tid >> 4, vc4 = (tid & 15) * 4;

    float acc[2][4][4];
#pragma unroll
    for (int i = 0; i < 2; i++)
#pragma unroll
        for (int j = 0; j < 4; j++)
#pragma unroll
            for (int c = 0; c < 4; c++) acc[i][j][c] = 0.f;

    {
        cp16(&Ps[0][prow][pc4],      &P[(size_t)(m0 + prow) * LLEN + pc4]);
        cp16(&Ps[0][prow + 64][pc4], &P[(size_t)(m0 + prow + 64) * LLEN + pc4]);
        cp16(&Vs[0][vrow][vc4],      &V[(size_t)vrow * DHEAD + vc4]);
        cp_commit();
    }

    const int NIT = LLEN / 16;
    for (int it = 0; it < NIT; it++) {
        const int buf = it & 1;
        if (it + 1 < NIT) {
            const int k0 = (it + 1) * 16;
            cp16(&Ps[buf ^ 1][prow][pc4],      &P[(size_t)(m0 + prow) * LLEN + k0 + pc4]);
            cp16(&Ps[buf ^ 1][prow + 64][pc4], &P[(size_t)(m0 + prow + 64) * LLEN + k0 + pc4]);
            cp16(&Vs[buf ^ 1][vrow][vc4],      &V[(size_t)(k0 + vrow) * DHEAD + vc4]);
            cp_commit();
            cp_wait<1>();
        } else {
            cp_wait<0>();
        }
        __syncthreads();

#pragma unroll
        for (int ks = 0; ks < 16; ks += 8) {
            unsigned af[2][4], bf[4][2];
#pragma unroll
            for (int i = 0; i < 2; i++) {
                int mr = wm * 32 + i * 16;
                af[i][0] = f2tf32(Ps[buf][mr + g][ks + t]);
                af[i][1] = f2tf32(Ps[buf][mr + g + 8][ks + t]);
                af[i][2] = f2tf32(Ps[buf][mr + g][ks + t + 4]);
                af[i][3] = f2tf32(Ps[buf][mr + g + 8][ks + t + 4]);
            }
#pragma unroll
            for (int j = 0; j < 4; j++) {
                int nr = wn * 32 + j * 8;
                bf[j][0] = f2tf32(Vs[buf][ks + t][nr + g]);
                bf[j][1] = f2tf32(Vs[buf][ks + t + 4][nr + g]);
            }
#pragma unroll
            for (int i = 0; i < 2; i++)
#pragma unroll
                for (int j = 0; j < 4; j++) mma_tf32(acc[i][j], af[i], bf[j]);
        }
        __syncthreads();
    }

    const int b = bh / NH, h = bh % NH;
#pragma unroll
    for (int i = 0; i < 2; i++) {
        int l0 = m0 + wm * 32 + i * 16 + g;
#pragma unroll
        for (int j = 0; j < 4; j++) {
            int d = wn * 32 + j * 8 + 2 * t;
            float2 v0 = make_float2(acc[i][j][0], acc[i][j][1]);
            float2 v1 = make_float2(acc[i][j][2], acc[i][j][3]);
            *(float2*)&g_ctx[((size_t)(b * LLEN + l0)) * DMODEL + h * 64 + d] = v0;
            *(float2*)&g_ctx[((size_t)(b * LLEN + l0 + 8)) * DMODEL + h * 64 + d] = v1;
        }
    }
}

// =========================================================================
// Kernel 4: output projection, cp.async 2-stage pipeline.  (R5, unchanged)
// =========================================================================
__global__ __launch_bounds__(256) void proj_mma_kernel(const float* __restrict__ Wo)
{
    __shared__ float As[2][128][20];
    __shared__ float Bs[2][16][136];

    const int tid  = threadIdx.x;
    const int warp = tid >> 5, lane = tid & 31;
    const int wm = warp >> 1, wn = warp & 1;
    const int g = lane >> 2, t = lane & 3;

    const int m0 = blockIdx.y * 128;
    const int n0 = blockIdx.x * 128;

    const int am0 = (tid * 2) >> 2,      ach0 = ((tid * 2) & 3) * 4;
    const int am1 = (tid * 2 + 1) >> 2,  ach1 = ((tid * 2 + 1) & 3) * 4;
    const int bk0 = (tid * 2) >> 5,      bch0 = ((tid * 2) & 31) * 4;
    const int bk1 = (tid * 2 + 1) >> 5,  bch1 = ((tid * 2 + 1) & 31) * 4;

    float acc[2][8][4];
#pragma unroll
    for (int i = 0; i < 2; i++)
#pragma unroll
        for (int j = 0; j < 8; j++)
#pragma unroll
            for (int c = 0; c < 4; c++) acc[i][j][c] = 0.f;

    cp16(&As[0][am0][ach0], &g_ctx[(size_t)(m0 + am0) * DMODEL + ach0]);
    cp16(&As[0][am1][ach1], &g_ctx[(size_t)(m0 + am1) * DMODEL + ach1]);
    cp16(&Bs[0][bk0][bch0], &Wo[(size_t)bk0 * DMODEL + n0 + bch0]);
    cp16(&Bs[0][bk1][bch1], &Wo[(size_t)bk1 * DMODEL + n0 + bch1]);
    cp_commit();

    const int NIT = DMODEL / 16;
    for (int it = 0; it < NIT; it++) {
        const int buf = it & 1;
        if (it + 1 < NIT) {
            const int k0 = (it + 1) * 16;
            cp16(&As[buf ^ 1][am0][ach0], &g_ctx[(size_t)(m0 + am0) * DMODEL + k0 + ach0]);
            cp16(&As[buf ^ 1][am1][ach1], &g_ctx[(size_t)(m0 + am1) * DMODEL + k0 + ach1]);
            cp16(&Bs[buf ^ 1][bk0][bch0], &Wo[(size_t)(k0 + bk0) * DMODEL + n0 + bch0]);
            cp16(&Bs[buf ^ 1][bk1][bch1], &Wo[(size_t)(k0 + bk1) * DMODEL + n0 + bch1]);
            cp_commit();
            cp_wait<1>();
        } else {
            cp_wait<0>();
        }
        __syncthreads();

#pragma unroll
        for (int ks = 0; ks < 16; ks += 8) {
            unsigned af[2][4], bf[8][2];
#pragma unroll
            for (int i = 0; i < 2; i++) {
                int mr = wm * 32 + i * 16;
                af[i][0] = f2tf32(As[buf][mr + g][ks + t]);
                af[i][1] = f2tf32(As[buf][mr + g + 8][ks + t]);
                af[i][2] = f2tf32(As[buf][mr + g][ks + t + 4]);
                af[i][3] = f2tf32(As[buf][mr + g + 8][ks + t + 4]);
            }
#pragma unroll
            for (int j = 0; j < 8; j++) {
                int nr = wn * 64 + j * 8;
                bf[j][0] = f2tf32(Bs[buf][ks + t][nr + g]);
                bf[j][1] = f2tf32(Bs[buf][ks + t + 4][nr + g]);
            }
#pragma unroll
            for (int i = 0; i < 2; i++)
#pragma unroll
                for (int j = 0; j < 8; j++) mma_tf32(acc[i][j], af[i], bf[j]);
        }
        __syncthreads();
    }

#pragma unroll
    for (int i = 0; i < 2; i++) {
        int r0 = m0 + wm * 32 + i * 16 + g;
#pragma unroll
        for (int j = 0; j < 8; j++) {
            int c = n0 + wn * 64 + j * 8 + 2 * t;
            float2 v0 = make_float2(acc[i][j][0], acc[i][j][1]);
            float2 v1 = make_float2(acc[i][j][2], acc[i][j][3]);
            *(float2*)&g_proj[(size_t)r0 * DMODEL + c] = v0;
            *(float2*)&g_proj[(size_t)(r0 + 8) * DMODEL + c] = v1;
        }
    }
}

// =========================================================================
// Kernel 5: residual + LayerNorm (unchanged).
// =========================================================================
__global__ void ln_kernel(const float* __restrict__ X,
                          const float* __restrict__ gamma,
                          const float* __restrict__ beta,
                          float* __restrict__ out)
{
    const int row = blockIdx.x;
    const int tid = threadIdx.x;
    const float* __restrict__ pr = g_proj + (size_t)row * DMODEL;
    const float* __restrict__ xr = X + (size_t)row * DMODEL;

    float4 p = reinterpret_cast<const float4*>(pr)[tid];
    float4 x = reinterpret_cast<const float4*>(xr)[tid];
    float y0 = p.x + x.x, y1 = p.y + x.y, y2 = p.z + x.z, y3 = p.w + x.w;

    __shared__ float red[8];
    float s = y0 + y1 + y2 + y3;
#pragma unroll
    for (int o = 16; o > 0; o >>= 1) s += __shfl_xor_sync(0xffffffffu, s, o);
    if ((tid & 31) == 0) red[tid >> 5] = s;
    __syncthreads();
    float tot = red[0];
#pragma unroll
    for (int w = 1; w < 8; w++) tot += red[w];
    const float mu = tot * (1.0f / DMODEL);
    __syncthreads();

    float d0 = y0 - mu, d1 = y1 - mu, d2 = y2 - mu, d3 = y3 - mu;
    float sq = d0 * d0 + d1 * d1 + d2 * d2 + d3 * d3;
#pragma unroll
    for (int o = 16; o > 0; o >>= 1) sq += __shfl_xor_sync(0xffffffffu, sq, o);
    if ((tid & 31) == 0) red[tid >> 5] = sq;
    __syncthreads();
    float tot2 = red[0];
#pragma unroll
    for (int w = 1; w < 8; w++) tot2 += red[w];
    const float var = tot2 * (1.0f / DMODEL);
    const float inv = rsqrtf(var + 1e-6f);

    const int c = tid * 4;
    float* __restrict__ orow = out + (size_t)row * DMODEL;
    orow[c + 0] = d0 * inv * gamma[c + 0] + beta[c + 0];
    orow[c + 1] = d1 * inv * gamma[c + 1] + beta[c + 1];
    orow[c + 2] = d2 * inv * gamma[c + 2] + beta[c + 2];
    orow[c + 3] = d3 * inv * gamma[c + 3] + beta[c + 3];
}

// =========================================================================
extern "C" void kernel_launch(void* const* d_in, const int* in_sizes, int n_in,
                              void* d_out, int out_size)
{
    const float* X     = (const float*)d_in[0];
    const int*   mask  = (const int*)d_in[1];
    const float* Wq    = (const float*)d_in[2];
    const float* Wk    = (const float*)d_in[3];
    const float* Wv    = (const float*)d_in[4];
    const float* Wo    = (const float*)d_in[5];
    const float* gamma = (const float*)d_in[6];
    const float* beta  = (const float*)d_in[7];
    float* out = (float*)d_out;

    const long long LN_N   = (long long)BB * LLEN * DMODEL;
    const long long ATTN_N = (long long)BB * NH * LLEN * LLEN;
    float* attn_ptr = ((long long)out_size >= LN_N + ATTN_N) ? (out + LN_N) : nullptr;

    qkv_mma_kernel<<<dim3(24, 64), 256>>>(X, Wq, Wk, Wv);
    fused_attn_kernel<<<dim3(32, BB * NH), 512>>>(mask, attn_ptr);
    pv_mma_kernel<<<dim3(8, BB * NH), 256>>>(attn_ptr);
    proj_mma_kernel<<<dim3(8, 64), 256>>>(Wo);
    ln_kernel<<<BB * LLEN, 256>>>(X, gamma, beta, out);
}